// round 1
// baseline (speedup 1.0000x reference)
#include <cuda_runtime.h>
#include <math.h>
#include <float.h>

// Shapes
#define B_  64
#define C_  256
#define HW_ 4096        // 64*64
#define K_  21
#define BK_ (B_*K_)     // 1344
#define BC_ (B_*C_)     // 16384
#define KC_ (K_*C_)     // 5376

// Scratch (static device allocations — allowed)
__device__ float g_dot[BC_];
__device__ float g_S1[B_*K_*C_];
__device__ float g_S2[B_*K_*C_];
__device__ int4  g_rect1[BK_];
__device__ int4  g_rect2[BK_];
__device__ float g_maxdot;
__device__ float g_sq[KC_];

// ---------------------------------------------------------------------------
// Kernel 1: ROI bounds per (b,k) for both pre tensors.
// left  = int(max(x-4,0)), right = int(min(x+4,63))   (exclusive upper)
// down  = int(max(y-4,0)), upper = int(min(y+4,63))
// ---------------------------------------------------------------------------
__global__ void bounds_kernel(const float* __restrict__ pre1,
                              const float* __restrict__ pre2) {
    int i = blockIdx.x * blockDim.x + threadIdx.x;
    if (i >= 2 * BK_) return;
    bool second = (i >= BK_);
    int j = second ? (i - BK_) : i;
    const float* p = second ? pre2 : pre1;
    float x = p[2 * j + 0];
    float y = p[2 * j + 1];
    int4 rc;
    rc.x = (int)fmaxf(x - 4.0f, 0.0f);   // left   (h)
    rc.y = (int)fminf(x + 4.0f, 63.0f);  // right  (h, excl)
    rc.z = (int)fmaxf(y - 4.0f, 0.0f);   // down   (w)
    rc.w = (int)fminf(y + 4.0f, 63.0f);  // upper  (w, excl)
    if (second) g_rect2[j] = rc; else g_rect1[j] = rc;
}

// ---------------------------------------------------------------------------
// Kernel 2: main pass. One block per (b,c) slice of [64,64].
// Computes dot[b,c] = sum f1*f2, and per-keypoint rect sums of f1 and f2.
// ---------------------------------------------------------------------------
__global__ __launch_bounds__(256) void pass1_kernel(const float* __restrict__ f1,
                                                    const float* __restrict__ f2) {
    __shared__ float s1[HW_];
    __shared__ float s2[HW_];
    __shared__ float red[8];

    int bc = blockIdx.x;            // = b*256 + c
    int b  = bc >> 8;
    int c  = bc & 255;
    size_t off = (size_t)bc * HW_;

    const float4* p1 = (const float4*)(f1 + off);
    const float4* p2 = (const float4*)(f2 + off);

    float dot = 0.0f;
    #pragma unroll
    for (int i = threadIdx.x; i < HW_ / 4; i += 256) {
        float4 a = p1[i];
        float4 d = p2[i];
        ((float4*)s1)[i] = a;
        ((float4*)s2)[i] = d;
        dot += a.x * d.x + a.y * d.y + a.z * d.z + a.w * d.w;
    }
    // block reduce dot
    #pragma unroll
    for (int o = 16; o; o >>= 1) dot += __shfl_xor_sync(0xffffffffu, dot, o);
    int warp = threadIdx.x >> 5, lane = threadIdx.x & 31;
    if (lane == 0) red[warp] = dot;
    __syncthreads();   // also publishes s1/s2 to all warps
    if (threadIdx.x == 0) {
        float s = 0.0f;
        #pragma unroll
        for (int i = 0; i < 8; i++) s += red[i];
        g_dot[bc] = s;
    }

    // rect sums: 42 reductions (21 keypoints x 2 tensors), warp-per-rect
    for (int r = warp; r < 2 * K_; r += 8) {
        bool second = (r >= K_);
        int k = second ? (r - K_) : r;
        int4 rc = second ? g_rect2[b * K_ + k] : g_rect1[b * K_ + k];
        const float* s = second ? s2 : s1;
        int nw = rc.w - rc.z;
        int n  = (rc.y - rc.x) * nw;
        float sum = 0.0f;
        for (int j = lane; j < n; j += 32) {
            int h = rc.x + j / nw;
            int w = rc.z + j % nw;
            sum += s[h * 64 + w];
        }
        #pragma unroll
        for (int o = 16; o; o >>= 1) sum += __shfl_xor_sync(0xffffffffu, sum, o);
        if (lane == 0) {
            float* dst = second ? g_S2 : g_S1;
            dst[((size_t)b * K_ + k) * C_ + c] = sum;
        }
    }
}

// ---------------------------------------------------------------------------
// Kernel 3: max over g_dot (16384 values), single block.
// ---------------------------------------------------------------------------
__global__ void maxdot_kernel() {
    __shared__ float red[8];
    float m = -FLT_MAX;
    for (int i = threadIdx.x; i < BC_; i += 256) m = fmaxf(m, g_dot[i]);
    #pragma unroll
    for (int o = 16; o; o >>= 1) m = fmaxf(m, __shfl_xor_sync(0xffffffffu, m, o));
    if ((threadIdx.x & 31) == 0) red[threadIdx.x >> 5] = m;
    __syncthreads();
    if (threadIdx.x == 0) {
        float s = red[0];
        #pragma unroll
        for (int i = 1; i < 8; i++) s = fmaxf(s, red[i]);
        g_maxdot = s;
    }
}

// ---------------------------------------------------------------------------
// Kernel 4: combine. grid = 21 (k), block = 256 (c).
// fea[k,c] = M_EMA * (1/B) * sum_b dot[b,c]/maxdot * S[b,k,c]/cnt[b,k] + (1-M)*val
// writes squared diff per (k,c) — deterministic (no float atomics).
// ---------------------------------------------------------------------------
__global__ __launch_bounds__(256) void final_kernel(const float* __restrict__ val1,
                                                    const float* __restrict__ val2) {
    int k = blockIdx.x;
    int c = threadIdx.x;
    float acc1 = 0.0f, acc2 = 0.0f;
    for (int b = 0; b < B_; b++) {
        float d = g_dot[b * C_ + c];
        int4 r1 = g_rect1[b * K_ + k];
        int4 r2 = g_rect2[b * K_ + k];
        float cnt1 = (float)((r1.y - r1.x) * (r1.w - r1.z));
        float cnt2 = (float)((r2.y - r2.x) * (r2.w - r2.z));
        size_t idx = ((size_t)b * K_ + k) * C_ + c;
        acc1 += d * g_S1[idx] / cnt1;
        acc2 += d * g_S2[idx] / cnt2;
    }
    float inv = 1.0f / ((float)B_ * g_maxdot);
    float fea1 = 0.999f * (acc1 * inv) + 0.001f * val1[0];
    float fea2 = 0.999f * (acc2 * inv) + 0.001f * val2[0];
    float df = fea1 - fea2;
    g_sq[k * C_ + c] = df * df;
}

// ---------------------------------------------------------------------------
// Kernel 5: mean over the 5376 squared diffs -> out[0]
// ---------------------------------------------------------------------------
__global__ void reduce_kernel(float* __restrict__ out) {
    __shared__ float red[8];
    float s = 0.0f;
    for (int i = threadIdx.x; i < KC_; i += 256) s += g_sq[i];
    #pragma unroll
    for (int o = 16; o; o >>= 1) s += __shfl_xor_sync(0xffffffffu, s, o);
    if ((threadIdx.x & 31) == 0) red[threadIdx.x >> 5] = s;
    __syncthreads();
    if (threadIdx.x == 0) {
        float t = 0.0f;
        #pragma unroll
        for (int i = 0; i < 8; i++) t += red[i];
        out[0] = t / (float)KC_;
    }
}

extern "C" void kernel_launch(void* const* d_in, const int* in_sizes, int n_in,
                              void* d_out, int out_size) {
    const float* f1   = (const float*)d_in[0];
    const float* f2   = (const float*)d_in[1];
    const float* pre1 = (const float*)d_in[2];
    const float* pre2 = (const float*)d_in[3];
    const float* val1 = (const float*)d_in[4];
    const float* val2 = (const float*)d_in[5];
    float* out = (float*)d_out;

    bounds_kernel<<<(2 * BK_ + 255) / 256, 256>>>(pre1, pre2);
    pass1_kernel<<<BC_, 256>>>(f1, f2);
    maxdot_kernel<<<1, 256>>>();
    final_kernel<<<K_, 256>>>(val1, val2);
    reduce_kernel<<<1, 256>>>(out);
}

// round 2
// speedup vs baseline: 1.3901x; 1.3901x over previous
#include <cuda_runtime.h>
#include <math.h>
#include <float.h>

// Shapes
#define B_  64
#define C_  256
#define HW_ 4096        // 64*64
#define K_  21
#define BK_ (B_*K_)     // 1344
#define BC_ (B_*C_)     // 16384
#define KC_ (K_*C_)     // 5376
#define NB_ 8           // b-groups for final partial stage (64/8 = 8 b per block)

// Scratch (static device arrays — allowed)
__device__ float g_dot[BC_];
__device__ float g_S1[B_*K_*C_];
__device__ float g_S2[B_*K_*C_];
__device__ int4  g_rect1[BK_];
__device__ int4  g_rect2[BK_];
__device__ float g_icnt1[BK_];   // 1/count
__device__ float g_icnt2[BK_];
__device__ float g_maxdot;
__device__ float g_part1[K_*NB_*C_];
__device__ float g_part2[K_*NB_*C_];
__device__ float g_sq[KC_];

// ---------------------------------------------------------------------------
// Kernel 1: ROI bounds + inverse counts per (b,k), both pre tensors.
// ---------------------------------------------------------------------------
__global__ void bounds_kernel(const float* __restrict__ pre1,
                              const float* __restrict__ pre2) {
    int i = blockIdx.x * blockDim.x + threadIdx.x;
    if (i >= 2 * BK_) return;
    bool second = (i >= BK_);
    int j = second ? (i - BK_) : i;
    const float* p = second ? pre2 : pre1;
    float x = p[2 * j + 0];
    float y = p[2 * j + 1];
    int4 rc;
    rc.x = (int)fmaxf(x - 4.0f, 0.0f);   // left   (h)
    rc.y = (int)fminf(x + 4.0f, 63.0f);  // right  (h, excl)
    rc.z = (int)fmaxf(y - 4.0f, 0.0f);   // down   (w)
    rc.w = (int)fminf(y + 4.0f, 63.0f);  // upper  (w, excl)
    float icnt = 1.0f / (float)((rc.y - rc.x) * (rc.w - rc.z));
    if (second) { g_rect2[j] = rc; g_icnt2[j] = icnt; }
    else        { g_rect1[j] = rc; g_icnt1[j] = icnt; }
}

// ---------------------------------------------------------------------------
// Kernel 2: main pass. One block per (b,c) slice of [64,64].
// dot[b,c] = sum f1*f2; per-keypoint rect sums of f1 and f2.
// ---------------------------------------------------------------------------
__global__ __launch_bounds__(256) void pass1_kernel(const float* __restrict__ f1,
                                                    const float* __restrict__ f2) {
    __shared__ float s1[HW_];
    __shared__ float s2[HW_];
    __shared__ float red[8];

    int bc = blockIdx.x;            // = b*256 + c
    int b  = bc >> 8;
    int c  = bc & 255;
    size_t off = (size_t)bc * HW_;

    const float4* p1 = (const float4*)(f1 + off);
    const float4* p2 = (const float4*)(f2 + off);

    float dot = 0.0f;
    #pragma unroll
    for (int i = threadIdx.x; i < HW_ / 4; i += 256) {
        float4 a = __ldcs(p1 + i);   // streaming: read-once data
        float4 d = __ldcs(p2 + i);
        ((float4*)s1)[i] = a;
        ((float4*)s2)[i] = d;
        dot += a.x * d.x + a.y * d.y + a.z * d.z + a.w * d.w;
    }
    // block reduce dot
    #pragma unroll
    for (int o = 16; o; o >>= 1) dot += __shfl_xor_sync(0xffffffffu, dot, o);
    int warp = threadIdx.x >> 5, lane = threadIdx.x & 31;
    if (lane == 0) red[warp] = dot;
    __syncthreads();   // also publishes s1/s2 to all warps
    if (threadIdx.x == 0) {
        float s = 0.0f;
        #pragma unroll
        for (int i = 0; i < 8; i++) s += red[i];
        g_dot[bc] = s;
    }

    // rect sums: 42 reductions (21 keypoints x 2 tensors), warp-per-rect
    for (int r = warp; r < 2 * K_; r += 8) {
        bool second = (r >= K_);
        int k = second ? (r - K_) : r;
        int4 rc = second ? g_rect2[b * K_ + k] : g_rect1[b * K_ + k];
        const float* s = second ? s2 : s1;
        int nw = rc.w - rc.z;
        int n  = (rc.y - rc.x) * nw;
        float sum = 0.0f;
        for (int j = lane; j < n; j += 32) {
            int h = rc.x + j / nw;
            int w = rc.z + j % nw;
            sum += s[h * 64 + w];
        }
        #pragma unroll
        for (int o = 16; o; o >>= 1) sum += __shfl_xor_sync(0xffffffffu, sum, o);
        if (lane == 0) {
            float* dst = second ? g_S2 : g_S1;
            dst[((size_t)b * K_ + k) * C_ + c] = sum;
        }
    }
}

// ---------------------------------------------------------------------------
// Kernel 3: max over g_dot (16384 values), single block.
// ---------------------------------------------------------------------------
__global__ void maxdot_kernel() {
    __shared__ float red[8];
    float m = -FLT_MAX;
    for (int i = threadIdx.x; i < BC_; i += 256) m = fmaxf(m, g_dot[i]);
    #pragma unroll
    for (int o = 16; o; o >>= 1) m = fmaxf(m, __shfl_xor_sync(0xffffffffu, m, o));
    if ((threadIdx.x & 31) == 0) red[threadIdx.x >> 5] = m;
    __syncthreads();
    if (threadIdx.x == 0) {
        float s = red[0];
        #pragma unroll
        for (int i = 1; i < 8; i++) s = fmaxf(s, red[i]);
        g_maxdot = s;
    }
}

// ---------------------------------------------------------------------------
// Kernel 4a: partial accumulate over b.
// grid = (K_, NB_), block = 256 (c). Each block sums 8 b-values.
// part[k, by, c] = sum_{b in group} dot[b,c] * S[b,k,c] * icnt[b,k]
// ---------------------------------------------------------------------------
__global__ __launch_bounds__(256) void final_part_kernel() {
    int k  = blockIdx.x;
    int by = blockIdx.y;
    int c  = threadIdx.x;
    int b0 = by * (B_ / NB_);
    float acc1 = 0.0f, acc2 = 0.0f;
    #pragma unroll
    for (int j = 0; j < B_ / NB_; j++) {
        int b = b0 + j;
        float d  = g_dot[b * C_ + c];
        float i1 = g_icnt1[b * K_ + k];
        float i2 = g_icnt2[b * K_ + k];
        size_t idx = ((size_t)b * K_ + k) * C_ + c;
        acc1 += d * g_S1[idx] * i1;
        acc2 += d * g_S2[idx] * i2;
    }
    int pidx = (k * NB_ + by) * C_ + c;
    g_part1[pidx] = acc1;
    g_part2[pidx] = acc2;
}

// ---------------------------------------------------------------------------
// Kernel 4b: combine partials, EMA, squared diff. grid = K_, block = 256.
// ---------------------------------------------------------------------------
__global__ __launch_bounds__(256) void final_combine_kernel(const float* __restrict__ val1,
                                                            const float* __restrict__ val2) {
    int k = blockIdx.x;
    int c = threadIdx.x;
    float acc1 = 0.0f, acc2 = 0.0f;
    #pragma unroll
    for (int j = 0; j < NB_; j++) {
        int pidx = (k * NB_ + j) * C_ + c;
        acc1 += g_part1[pidx];
        acc2 += g_part2[pidx];
    }
    float inv = 1.0f / ((float)B_ * g_maxdot);
    float fea1 = 0.999f * (acc1 * inv) + 0.001f * val1[0];
    float fea2 = 0.999f * (acc2 * inv) + 0.001f * val2[0];
    float df = fea1 - fea2;
    g_sq[k * C_ + c] = df * df;
}

// ---------------------------------------------------------------------------
// Kernel 5: mean over the 5376 squared diffs -> out[0]
// ---------------------------------------------------------------------------
__global__ void reduce_kernel(float* __restrict__ out) {
    __shared__ float red[8];
    float s = 0.0f;
    for (int i = threadIdx.x; i < KC_; i += 256) s += g_sq[i];
    #pragma unroll
    for (int o = 16; o; o >>= 1) s += __shfl_xor_sync(0xffffffffu, s, o);
    if ((threadIdx.x & 31) == 0) red[threadIdx.x >> 5] = s;
    __syncthreads();
    if (threadIdx.x == 0) {
        float t = 0.0f;
        #pragma unroll
        for (int i = 0; i < 8; i++) t += red[i];
        out[0] = t / (float)KC_;
    }
}

extern "C" void kernel_launch(void* const* d_in, const int* in_sizes, int n_in,
                              void* d_out, int out_size) {
    const float* f1   = (const float*)d_in[0];
    const float* f2   = (const float*)d_in[1];
    const float* pre1 = (const float*)d_in[2];
    const float* pre2 = (const float*)d_in[3];
    const float* val1 = (const float*)d_in[4];
    const float* val2 = (const float*)d_in[5];
    float* out = (float*)d_out;

    bounds_kernel<<<(2 * BK_ + 255) / 256, 256>>>(pre1, pre2);
    pass1_kernel<<<BC_, 256>>>(f1, f2);
    maxdot_kernel<<<1, 256>>>();
    final_part_kernel<<<dim3(K_, NB_), 256>>>();
    final_combine_kernel<<<K_, 256>>>(val1, val2);
    reduce_kernel<<<1, 256>>>(out);
}

// round 3
// speedup vs baseline: 1.6285x; 1.1714x over previous
#include <cuda_runtime.h>
#include <math.h>
#include <float.h>

// Shapes
#define B_  64
#define C_  256
#define HW_ 4096        // 64*64
#define K_  21
#define BK_ (B_*K_)     // 1344
#define BC_ (B_*C_)     // 16384
#define KC_ (K_*C_)     // 5376
#define NB_ 8           // b-groups for final partial stage

// Scratch (static device arrays — allowed)
__device__ float g_dot[BC_];
__device__ float g_S1[B_*K_*C_];
__device__ float g_S2[B_*K_*C_];
__device__ float g_maxdot;
__device__ float g_part1[K_*NB_*C_];
__device__ float g_part2[K_*NB_*C_];
__device__ float g_sq[KC_];

// Rect from keypoint (x,y): [left,right) x [down,upper), truncation after clip.
// Guaranteed: 4 <= nh,nw <= 8.
__device__ __forceinline__ int4 make_rect(float x, float y) {
    int4 rc;
    rc.x = (int)fmaxf(x - 4.0f, 0.0f);   // left   (h)
    rc.y = (int)fminf(x + 4.0f, 63.0f);  // right  (h, excl)
    rc.z = (int)fmaxf(y - 4.0f, 0.0f);   // down   (w)
    rc.w = (int)fminf(y + 4.0f, 63.0f);  // upper  (w, excl)
    return rc;
}

// ---------------------------------------------------------------------------
// Kernel 1: main pass. One block per (b,c) slice of [64,64].
// dot[b,c] = sum f1*f2; per-keypoint rect sums of f1 and f2.
// Rects computed in-block from pre (no separate bounds kernel).
// ---------------------------------------------------------------------------
__global__ __launch_bounds__(256) void pass1_kernel(const float* __restrict__ f1,
                                                    const float* __restrict__ f2,
                                                    const float* __restrict__ pre1,
                                                    const float* __restrict__ pre2) {
    __shared__ float s1[HW_];
    __shared__ float s2[HW_];
    __shared__ float red[8];
    __shared__ int4  s_rect[2 * K_];

    int bc = blockIdx.x;            // = b*256 + c
    int b  = bc >> 8;
    int c  = bc & 255;
    size_t off = (size_t)bc * HW_;

    // Threads 0..41: rects for f1; 42..83: rects for f2.
    if (threadIdx.x < 2 * K_) {
        int t = threadIdx.x;
        bool second = (t >= K_);
        int k = second ? (t - K_) : t;
        const float* p = second ? pre2 : pre1;
        float x = __ldg(&p[(b * K_ + k) * 2 + 0]);
        float y = __ldg(&p[(b * K_ + k) * 2 + 1]);
        s_rect[t] = make_rect(x, y);
    }

    const float4* p1 = (const float4*)(f1 + off);
    const float4* p2 = (const float4*)(f2 + off);

    float dot = 0.0f;
    #pragma unroll
    for (int i = threadIdx.x; i < HW_ / 4; i += 256) {
        float4 a = __ldcs(p1 + i);   // streaming: read-once data
        float4 d = __ldcs(p2 + i);
        ((float4*)s1)[i] = a;
        ((float4*)s2)[i] = d;
        dot += a.x * d.x + a.y * d.y + a.z * d.z + a.w * d.w;
    }
    // block reduce dot
    #pragma unroll
    for (int o = 16; o; o >>= 1) dot += __shfl_xor_sync(0xffffffffu, dot, o);
    int warp = threadIdx.x >> 5, lane = threadIdx.x & 31;
    if (lane == 0) red[warp] = dot;
    __syncthreads();   // publishes s1/s2/s_rect/red to all warps
    if (threadIdx.x == 0) {
        float s = 0.0f;
        #pragma unroll
        for (int i = 0; i < 8; i++) s += red[i];
        g_dot[bc] = s;
    }

    // rect sums: 42 reductions, warp-per-rect, lane -> (dh,dw) mapping
    // rect is at most 8x8; two passes of 4 rows x 8 cols. No divides.
    int dh = lane >> 3;       // 0..3
    int dw = lane & 7;        // 0..7
    for (int r = warp; r < 2 * K_; r += 8) {
        int4 rc = s_rect[r];
        const float* s = (r >= K_) ? s2 : s1;
        int nh = rc.y - rc.x;
        int nw = rc.w - rc.z;
        int base = rc.x * 64 + rc.z;
        float sum = 0.0f;
        bool wok = (dw < nw);
        if (wok && dh     < nh) sum += s[base +  dh      * 64 + dw];
        if (wok && dh + 4 < nh) sum += s[base + (dh + 4) * 64 + dw];
        #pragma unroll
        for (int o = 16; o; o >>= 1) sum += __shfl_xor_sync(0xffffffffu, sum, o);
        if (lane == 0) {
            int k = (r >= K_) ? (r - K_) : r;
            float* dst = (r >= K_) ? g_S2 : g_S1;
            dst[((size_t)b * K_ + k) * C_ + c] = sum;
        }
    }
}

// ---------------------------------------------------------------------------
// Kernel 2: max over g_dot (16384 values), single block.
// ---------------------------------------------------------------------------
__global__ void maxdot_kernel() {
    __shared__ float red[8];
    float m = -FLT_MAX;
    for (int i = threadIdx.x; i < BC_; i += 256) m = fmaxf(m, g_dot[i]);
    #pragma unroll
    for (int o = 16; o; o >>= 1) m = fmaxf(m, __shfl_xor_sync(0xffffffffu, m, o));
    if ((threadIdx.x & 31) == 0) red[threadIdx.x >> 5] = m;
    __syncthreads();
    if (threadIdx.x == 0) {
        float s = red[0];
        #pragma unroll
        for (int i = 1; i < 8; i++) s = fmaxf(s, red[i]);
        g_maxdot = s;
    }
}

// ---------------------------------------------------------------------------
// Kernel 3: partial accumulate over b. grid = (K_, NB_), block = 256 (c).
// icnt recomputed inline from pre (broadcast loads, deterministic identical math).
// ---------------------------------------------------------------------------
__global__ __launch_bounds__(256) void final_part_kernel(const float* __restrict__ pre1,
                                                         const float* __restrict__ pre2) {
    int k  = blockIdx.x;
    int by = blockIdx.y;
    int c  = threadIdx.x;
    int b0 = by * (B_ / NB_);
    float acc1 = 0.0f, acc2 = 0.0f;
    #pragma unroll
    for (int j = 0; j < B_ / NB_; j++) {
        int b = b0 + j;
        int4 r1 = make_rect(__ldg(&pre1[(b * K_ + k) * 2]), __ldg(&pre1[(b * K_ + k) * 2 + 1]));
        int4 r2 = make_rect(__ldg(&pre2[(b * K_ + k) * 2]), __ldg(&pre2[(b * K_ + k) * 2 + 1]));
        float i1 = 1.0f / (float)((r1.y - r1.x) * (r1.w - r1.z));
        float i2 = 1.0f / (float)((r2.y - r2.x) * (r2.w - r2.z));
        float d  = g_dot[b * C_ + c];
        size_t idx = ((size_t)b * K_ + k) * C_ + c;
        acc1 += d * g_S1[idx] * i1;
        acc2 += d * g_S2[idx] * i2;
    }
    int pidx = (k * NB_ + by) * C_ + c;
    g_part1[pidx] = acc1;
    g_part2[pidx] = acc2;
}

// ---------------------------------------------------------------------------
// Kernel 4: combine partials, EMA, squared diff. grid = K_, block = 256.
// ---------------------------------------------------------------------------
__global__ __launch_bounds__(256) void final_combine_kernel(const float* __restrict__ val1,
                                                            const float* __restrict__ val2) {
    int k = blockIdx.x;
    int c = threadIdx.x;
    float acc1 = 0.0f, acc2 = 0.0f;
    #pragma unroll
    for (int j = 0; j < NB_; j++) {
        int pidx = (k * NB_ + j) * C_ + c;
        acc1 += g_part1[pidx];
        acc2 += g_part2[pidx];
    }
    float inv = 1.0f / ((float)B_ * g_maxdot);
    float fea1 = 0.999f * (acc1 * inv) + 0.001f * val1[0];
    float fea2 = 0.999f * (acc2 * inv) + 0.001f * val2[0];
    float df = fea1 - fea2;
    g_sq[k * C_ + c] = df * df;
}

// ---------------------------------------------------------------------------
// Kernel 5: mean over the 5376 squared diffs -> out[0]
// ---------------------------------------------------------------------------
__global__ void reduce_kernel(float* __restrict__ out) {
    __shared__ float red[8];
    float s = 0.0f;
    for (int i = threadIdx.x; i < KC_; i += 256) s += g_sq[i];
    #pragma unroll
    for (int o = 16; o; o >>= 1) s += __shfl_xor_sync(0xffffffffu, s, o);
    if ((threadIdx.x & 31) == 0) red[threadIdx.x >> 5] = s;
    __syncthreads();
    if (threadIdx.x == 0) {
        float t = 0.0f;
        #pragma unroll
        for (int i = 0; i < 8; i++) t += red[i];
        out[0] = t / (float)KC_;
    }
}

extern "C" void kernel_launch(void* const* d_in, const int* in_sizes, int n_in,
                              void* d_out, int out_size) {
    const float* f1   = (const float*)d_in[0];
    const float* f2   = (const float*)d_in[1];
    const float* pre1 = (const float*)d_in[2];
    const float* pre2 = (const float*)d_in[3];
    const float* val1 = (const float*)d_in[4];
    const float* val2 = (const float*)d_in[5];
    float* out = (float*)d_out;

    pass1_kernel<<<BC_, 256>>>(f1, f2, pre1, pre2);
    maxdot_kernel<<<1, 256>>>();
    final_part_kernel<<<dim3(K_, NB_), 256>>>(pre1, pre2);
    final_combine_kernel<<<K_, 256>>>(val1, val2);
    reduce_kernel<<<1, 256>>>(out);
}